// round 5
// baseline (speedup 1.0000x reference)
#include <cuda_runtime.h>
#include <cuda_fp16.h>

#define N_NODES 50000
#define E_EDGES 800000
#define E2      (2 * E_EDGES)
#define D_DIM   200
#define C_DIM   10
#define NF4     (D_DIM / 4)     // 50 float4 per fp32 W0 row
#define NH4     (D_DIM / 8)     // 25 uint4 (8 halves) per fp16 W0 row
#define CAP     96              // per-row bucket capacity (deg ~ Poisson(32))
#define GP4     3               // g padded to 12 floats = 3 float4

// ---- scratch (__device__ globals; allocation-free rule) --------------------
__device__ int    g_cnt[N_NODES];
__device__ int2   g_adj[(size_t)N_NODES * CAP];        // {col, val bits}, 38.4 MB
__device__ uint4  g_W0h[(size_t)N_NODES * NH4];        // fp16 W0 copy, 20 MB
__device__ float4 g_gv[(size_t)N_NODES * GP4];         // relu(h)@W1, padded, 2.4 MB

// ---------------------------------------------------------------------------
// Convert W0 fp32 -> fp16 shadow (gather format). 8 halves per uint4.
// ---------------------------------------------------------------------------
__global__ void k_convert(const float4* __restrict__ W0v) {
    const int total = N_NODES * NH4;                   // 1.25M uint4
    int i = blockIdx.x * blockDim.x + threadIdx.x;
    const int stride = gridDim.x * blockDim.x;
    for (; i < total; i += stride) {
        const float4 f0 = W0v[2 * i];
        const float4 f1 = W0v[2 * i + 1];
        __half2 h0 = __floats2half2_rn(f0.x, f0.y);
        __half2 h1 = __floats2half2_rn(f0.z, f0.w);
        __half2 h2 = __floats2half2_rn(f1.x, f1.y);
        __half2 h3 = __floats2half2_rn(f1.z, f1.w);
        uint4 q;
        q.x = *(unsigned*)&h0;
        q.y = *(unsigned*)&h1;
        q.z = *(unsigned*)&h2;
        q.w = *(unsigned*)&h3;
        g_W0h[i] = q;
    }
}

// ---------------------------------------------------------------------------
// Scatter edges into per-row buckets (atomic slot claim; order irrelevant).
// ---------------------------------------------------------------------------
__global__ void k_scatter(const int*   __restrict__ rows0,
                          const int*   __restrict__ cols0,
                          const float* __restrict__ vals0,
                          const int*   __restrict__ rows1,
                          const int*   __restrict__ cols1,
                          const float* __restrict__ vals1) {
    const int e = blockIdx.x * blockDim.x + threadIdx.x;
    if (e >= E2) return;
    int r, c; float v;
    if (e < E_EDGES) { r = rows0[e]; c = cols0[e]; v = vals0[e]; }
    else { const int i = e - E_EDGES; r = rows1[i]; c = cols1[i]; v = vals1[i]; }
    const int pos = atomicAdd(&g_cnt[r], 1);
    if (pos < CAP)
        g_adj[(size_t)r * CAP + pos] = make_int2(c, __float_as_int(v));
}

// ---------------------------------------------------------------------------
// Fused layer 1 (one warp per row):
//   h = c0*W0_fp32[row] + sum_e v_e * W0_fp16[col_e]   (fp32 accumulate)
//   g[row] = relu(h) @ W1
// Lane k<25 owns h[8k .. 8k+7]. Edge gather = one LDG.128 of 8 halves/lane.
// ---------------------------------------------------------------------------
__global__ void k_layer1(const float* __restrict__ W0,
                         const float* __restrict__ W1,
                         const float* __restrict__ eps0) {
    __shared__ float sW1[D_DIM * C_DIM];               // 8 KB
    for (int i = threadIdx.x; i < D_DIM * C_DIM; i += blockDim.x)
        sW1[i] = W1[i];
    __syncthreads();

    const int row  = blockIdx.x * (blockDim.x >> 5) + (threadIdx.x >> 5);
    const int lane = threadIdx.x & 31;
    const bool own = (lane < NH4);                     // lanes 0..24

    const float4* __restrict__ W0v = (const float4*)W0;
    const float c0 = 0.1f * (1.0f + eps0[0]);

    // self-term in fp32
    float a[8] = {0,0,0,0,0,0,0,0};
    if (own) {
        const float4 s0 = W0v[(size_t)row * NF4 + 2 * lane];
        const float4 s1 = W0v[(size_t)row * NF4 + 2 * lane + 1];
        a[0] = c0 * s0.x; a[1] = c0 * s0.y; a[2] = c0 * s0.z; a[3] = c0 * s0.w;
        a[4] = c0 * s1.x; a[5] = c0 * s1.y; a[6] = c0 * s1.z; a[7] = c0 * s1.w;
    }

    const int deg = min(g_cnt[row], CAP);
    const int2* __restrict__ adj = g_adj + (size_t)row * CAP;

    for (int base = 0; base < deg; base += 32) {
        const int n = min(32, deg - base);
        int2 ev = make_int2(0, 0);
        if (lane < n) ev = adj[base + lane];           // coalesced 8B/lane

        for (int j = 0; j < n; j++) {
            const int   c = __shfl_sync(0xffffffff, ev.x, j);
            const float v = __int_as_float(__shfl_sync(0xffffffff, ev.y, j));
            if (own) {
                const uint4 q = g_W0h[(size_t)c * NH4 + lane];  // 8 halves
                const float2 f0 = __half22float2(*(const __half2*)&q.x);
                const float2 f1 = __half22float2(*(const __half2*)&q.y);
                const float2 f2 = __half22float2(*(const __half2*)&q.z);
                const float2 f3 = __half22float2(*(const __half2*)&q.w);
                a[0] = fmaf(v, f0.x, a[0]); a[1] = fmaf(v, f0.y, a[1]);
                a[2] = fmaf(v, f1.x, a[2]); a[3] = fmaf(v, f1.y, a[3]);
                a[4] = fmaf(v, f2.x, a[4]); a[5] = fmaf(v, f2.y, a[5]);
                a[6] = fmaf(v, f3.x, a[6]); a[7] = fmaf(v, f3.y, a[7]);
            }
        }
    }

    // ReLU + project to C=10
    float acc[C_DIM];
    #pragma unroll
    for (int c = 0; c < C_DIM; c++) acc[c] = 0.0f;

    if (own) {
        #pragma unroll
        for (int k = 0; k < 8; k++) {
            const float hv = fmaxf(a[k], 0.0f);
            const int j = 8 * lane + k;
            #pragma unroll
            for (int c = 0; c < C_DIM; c++)
                acc[c] = fmaf(hv, sW1[j * C_DIM + c], acc[c]);
        }
    }

    #pragma unroll
    for (int c = 0; c < C_DIM; c++)
        #pragma unroll
        for (int off = 16; off > 0; off >>= 1)
            acc[c] += __shfl_xor_sync(0xffffffff, acc[c], off);

    float* __restrict__ grow = (float*)(g_gv + (size_t)row * GP4);
    #pragma unroll
    for (int c = 0; c < C_DIM; c++)
        if (lane == c) grow[c] = acc[c];
}

// ---------------------------------------------------------------------------
// Layer 2 (pull): out[row] = c1*g[row] + sum_e v_e * g[col_e]
// ---------------------------------------------------------------------------
__global__ void k_layer2(const float* __restrict__ eps1,
                         float*       __restrict__ out) {
    const int row  = blockIdx.x * (blockDim.x >> 5) + (threadIdx.x >> 5);
    const int lane = threadIdx.x & 31;

    const int deg = min(g_cnt[row], CAP);
    const int2* __restrict__ adj = g_adj + (size_t)row * CAP;

    float acc[C_DIM];
    #pragma unroll
    for (int k = 0; k < C_DIM; k++) acc[k] = 0.0f;

    for (int e = lane; e < deg; e += 32) {
        const int2  ev = adj[e];
        const float v  = __int_as_float(ev.y);
        const float4* __restrict__ src = g_gv + (size_t)ev.x * GP4;
        const float4 p0 = src[0];
        const float4 p1 = src[1];
        const float4 p2 = src[2];
        acc[0] = fmaf(v, p0.x, acc[0]); acc[1] = fmaf(v, p0.y, acc[1]);
        acc[2] = fmaf(v, p0.z, acc[2]); acc[3] = fmaf(v, p0.w, acc[3]);
        acc[4] = fmaf(v, p1.x, acc[4]); acc[5] = fmaf(v, p1.y, acc[5]);
        acc[6] = fmaf(v, p1.z, acc[6]); acc[7] = fmaf(v, p1.w, acc[7]);
        acc[8] = fmaf(v, p2.x, acc[8]); acc[9] = fmaf(v, p2.y, acc[9]);
    }

    #pragma unroll
    for (int k = 0; k < C_DIM; k++)
        #pragma unroll
        for (int off = 16; off > 0; off >>= 1)
            acc[k] += __shfl_xor_sync(0xffffffff, acc[k], off);

    const float c1 = 0.1f * (1.0f + eps1[0]);
    const float* __restrict__ grow = (const float*)(g_gv + (size_t)row * GP4);
    #pragma unroll
    for (int k = 0; k < C_DIM; k++)
        if (lane == k)
            out[(size_t)row * C_DIM + k] = fmaf(c1, grow[k], acc[k]);
}

// ---------------------------------------------------------------------------
// Launch. Inputs: x, rows0, cols0, vals0, rows1, cols1, vals1, W0, W1, eps0, eps1
// ---------------------------------------------------------------------------
extern "C" void kernel_launch(void* const* d_in, const int* in_sizes, int n_in,
                              void* d_out, int out_size) {
    const int*   rows0 = (const int*)  d_in[1];
    const int*   cols0 = (const int*)  d_in[2];
    const float* vals0 = (const float*)d_in[3];
    const int*   rows1 = (const int*)  d_in[4];
    const int*   cols1 = (const int*)  d_in[5];
    const float* vals1 = (const float*)d_in[6];
    const float* W0    = (const float*)d_in[7];
    const float* W1    = (const float*)d_in[8];
    const float* eps0  = (const float*)d_in[9];
    const float* eps1  = (const float*)d_in[10];
    float* out = (float*)d_out;

    void* cnt_ptr = nullptr;
    cudaGetSymbolAddress(&cnt_ptr, g_cnt);
    cudaMemsetAsync(cnt_ptr, 0, N_NODES * sizeof(int));

    k_convert<<<148 * 8, 256>>>((const float4*)W0);

    const int eb = (E2 + 255) / 256;                   // 6250
    k_scatter<<<eb, 256>>>(rows0, cols0, vals0, rows1, cols1, vals1);

    k_layer1<<<N_NODES / 8, 256>>>(W0, W1, eps0);      // warp per row
    k_layer2<<<N_NODES / 8, 256>>>(eps1, out);         // warp per row
}

// round 6
// speedup vs baseline: 1.1200x; 1.1200x over previous
#include <cuda_runtime.h>
#include <cuda_fp16.h>

#define N_NODES 50000
#define E_EDGES 800000
#define E2      (2 * E_EDGES)
#define D_DIM   200
#define C_DIM   10
#define NF4     (D_DIM / 4)     // 50 float4 per fp32 W0 row
#define NH4     (D_DIM / 8)     // 25 uint4 (8 halves) per fp16 W0 row
#define CAP     96              // per-row bucket capacity (deg ~ Poisson(32))

// ---- scratch (__device__ globals; allocation-free rule) --------------------
__device__ int    g_cnt[N_NODES];
__device__ int2   g_adj[(size_t)N_NODES * CAP];     // {col, val bits}, 38.4 MB
__device__ uint4  g_W0h[(size_t)N_NODES * NH4];     // fp16 W0 copy, 20 MB
__device__ uint4  g_gh[(size_t)N_NODES * 2];        // fp16 g, 16 halves/row (32 B), 3.2 MB

// ---------------------------------------------------------------------------
// Convert W0 fp32 -> fp16 shadow. 8 halves per uint4.
// ---------------------------------------------------------------------------
__global__ void k_convert(const float4* __restrict__ W0v) {
    const int total = N_NODES * NH4;
    int i = blockIdx.x * blockDim.x + threadIdx.x;
    const int stride = gridDim.x * blockDim.x;
    for (; i < total; i += stride) {
        const float4 f0 = W0v[2 * i];
        const float4 f1 = W0v[2 * i + 1];
        __half2 h0 = __floats2half2_rn(f0.x, f0.y);
        __half2 h1 = __floats2half2_rn(f0.z, f0.w);
        __half2 h2 = __floats2half2_rn(f1.x, f1.y);
        __half2 h3 = __floats2half2_rn(f1.z, f1.w);
        uint4 q;
        q.x = *(unsigned*)&h0; q.y = *(unsigned*)&h1;
        q.z = *(unsigned*)&h2; q.w = *(unsigned*)&h3;
        g_W0h[i] = q;
    }
}

// ---------------------------------------------------------------------------
// Scatter edges into per-row buckets.
// ---------------------------------------------------------------------------
__global__ void k_scatter(const int*   __restrict__ rows0,
                          const int*   __restrict__ cols0,
                          const float* __restrict__ vals0,
                          const int*   __restrict__ rows1,
                          const int*   __restrict__ cols1,
                          const float* __restrict__ vals1) {
    const int e = blockIdx.x * blockDim.x + threadIdx.x;
    if (e >= E2) return;
    int r, c; float v;
    if (e < E_EDGES) { r = rows0[e]; c = cols0[e]; v = vals0[e]; }
    else { const int i = e - E_EDGES; r = rows1[i]; c = cols1[i]; v = vals1[i]; }
    const int pos = atomicAdd(&g_cnt[r], 1);
    if (pos < CAP)
        g_adj[(size_t)r * CAP + pos] = make_int2(c, __float_as_int(v));
}

// ---------------------------------------------------------------------------
// Fused layer 1 (one warp per row, 4x-unrolled edge loop for MLP):
//   h = c0*W0[row] + sum_e v_e * W0h[col_e] ;  g[row] = fp16(relu(h) @ W1)
// ---------------------------------------------------------------------------
__device__ __forceinline__ void fma8(float a[8], float v, const uint4& q) {
    const float2 f0 = __half22float2(*(const __half2*)&q.x);
    const float2 f1 = __half22float2(*(const __half2*)&q.y);
    const float2 f2 = __half22float2(*(const __half2*)&q.z);
    const float2 f3 = __half22float2(*(const __half2*)&q.w);
    a[0] = fmaf(v, f0.x, a[0]); a[1] = fmaf(v, f0.y, a[1]);
    a[2] = fmaf(v, f1.x, a[2]); a[3] = fmaf(v, f1.y, a[3]);
    a[4] = fmaf(v, f2.x, a[4]); a[5] = fmaf(v, f2.y, a[5]);
    a[6] = fmaf(v, f3.x, a[6]); a[7] = fmaf(v, f3.y, a[7]);
}

__global__ void k_layer1(const float* __restrict__ W0,
                         const float* __restrict__ W1,
                         const float* __restrict__ eps0) {
    __shared__ float sW1[D_DIM * C_DIM];               // 8 KB
    for (int i = threadIdx.x; i < D_DIM * C_DIM; i += blockDim.x)
        sW1[i] = W1[i];
    __syncthreads();

    const int row  = blockIdx.x * (blockDim.x >> 5) + (threadIdx.x >> 5);
    const int lane = threadIdx.x & 31;
    const bool own = (lane < NH4);                     // lanes 0..24

    const float4* __restrict__ W0v = (const float4*)W0;
    const float c0 = 0.1f * (1.0f + eps0[0]);

    float a[8] = {0,0,0,0,0,0,0,0};
    if (own) {
        const float4 s0 = W0v[(size_t)row * NF4 + 2 * lane];
        const float4 s1 = W0v[(size_t)row * NF4 + 2 * lane + 1];
        a[0] = c0 * s0.x; a[1] = c0 * s0.y; a[2] = c0 * s0.z; a[3] = c0 * s0.w;
        a[4] = c0 * s1.x; a[5] = c0 * s1.y; a[6] = c0 * s1.z; a[7] = c0 * s1.w;
    }

    const int deg = min(g_cnt[row], CAP);
    const int2* __restrict__ adj = g_adj + (size_t)row * CAP;

    for (int base = 0; base < deg; base += 32) {
        const int n = min(32, deg - base);
        int2 ev = make_int2(0, 0);
        if (lane < n) ev = adj[base + lane];

        int j = 0;
        for (; j + 4 <= n; j += 4) {
            const int   c0i = __shfl_sync(0xffffffff, ev.x, j);
            const float v0  = __int_as_float(__shfl_sync(0xffffffff, ev.y, j));
            const int   c1i = __shfl_sync(0xffffffff, ev.x, j + 1);
            const float v1  = __int_as_float(__shfl_sync(0xffffffff, ev.y, j + 1));
            const int   c2i = __shfl_sync(0xffffffff, ev.x, j + 2);
            const float v2  = __int_as_float(__shfl_sync(0xffffffff, ev.y, j + 2));
            const int   c3i = __shfl_sync(0xffffffff, ev.x, j + 3);
            const float v3  = __int_as_float(__shfl_sync(0xffffffff, ev.y, j + 3));
            if (own) {
                const uint4 q0 = g_W0h[(size_t)c0i * NH4 + lane];
                const uint4 q1 = g_W0h[(size_t)c1i * NH4 + lane];
                const uint4 q2 = g_W0h[(size_t)c2i * NH4 + lane];
                const uint4 q3 = g_W0h[(size_t)c3i * NH4 + lane];
                fma8(a, v0, q0);
                fma8(a, v1, q1);
                fma8(a, v2, q2);
                fma8(a, v3, q3);
            }
        }
        for (; j < n; j++) {
            const int   c = __shfl_sync(0xffffffff, ev.x, j);
            const float v = __int_as_float(__shfl_sync(0xffffffff, ev.y, j));
            if (own) {
                const uint4 q = g_W0h[(size_t)c * NH4 + lane];
                fma8(a, v, q);
            }
        }
    }

    // ReLU + project to C=10
    float acc[C_DIM];
    #pragma unroll
    for (int c = 0; c < C_DIM; c++) acc[c] = 0.0f;

    if (own) {
        #pragma unroll
        for (int k = 0; k < 8; k++) {
            const float hv = fmaxf(a[k], 0.0f);
            const int j = 8 * lane + k;
            #pragma unroll
            for (int c = 0; c < C_DIM; c++)
                acc[c] = fmaf(hv, sW1[j * C_DIM + c], acc[c]);
        }
    }

    #pragma unroll
    for (int c = 0; c < C_DIM; c++)
        #pragma unroll
        for (int off = 16; off > 0; off >>= 1)
            acc[c] += __shfl_xor_sync(0xffffffff, acc[c], off);

    // pack g row to fp16: halves 0..9 used, row padded to 32 B (1 sector)
    if (lane == 0) {
        __half2 p0 = __floats2half2_rn(acc[0], acc[1]);
        __half2 p1 = __floats2half2_rn(acc[2], acc[3]);
        __half2 p2 = __floats2half2_rn(acc[4], acc[5]);
        __half2 p3 = __floats2half2_rn(acc[6], acc[7]);
        __half2 p4 = __floats2half2_rn(acc[8], acc[9]);
        uint4 q;
        q.x = *(unsigned*)&p0; q.y = *(unsigned*)&p1;
        q.z = *(unsigned*)&p2; q.w = *(unsigned*)&p3;
        g_gh[(size_t)row * 2] = q;
        uint4 q2 = make_uint4(*(unsigned*)&p4, 0u, 0u, 0u);
        g_gh[(size_t)row * 2 + 1] = q2;
    }
}

// ---------------------------------------------------------------------------
// Layer 2 (pull, fp16 g): out[row] = c1*g[row] + sum_e v_e * g[col_e]
// Gather per edge = uint4 + uint (one 32B sector).
// ---------------------------------------------------------------------------
__global__ void k_layer2(const float* __restrict__ eps1,
                         float*       __restrict__ out) {
    const int row  = blockIdx.x * (blockDim.x >> 5) + (threadIdx.x >> 5);
    const int lane = threadIdx.x & 31;

    const int deg = min(g_cnt[row], CAP);
    const int2* __restrict__ adj = g_adj + (size_t)row * CAP;

    float acc[C_DIM];
    #pragma unroll
    for (int k = 0; k < C_DIM; k++) acc[k] = 0.0f;

    for (int e = lane; e < deg; e += 32) {
        const int2  ev = adj[e];
        const float v  = __int_as_float(ev.y);
        const uint4 q0 = g_gh[(size_t)ev.x * 2];
        const unsigned q4 = *(const unsigned*)&g_gh[(size_t)ev.x * 2 + 1];
        const float2 f0 = __half22float2(*(const __half2*)&q0.x);
        const float2 f1 = __half22float2(*(const __half2*)&q0.y);
        const float2 f2 = __half22float2(*(const __half2*)&q0.z);
        const float2 f3 = __half22float2(*(const __half2*)&q0.w);
        const float2 f4 = __half22float2(*(const __half2*)&q4);
        acc[0] = fmaf(v, f0.x, acc[0]); acc[1] = fmaf(v, f0.y, acc[1]);
        acc[2] = fmaf(v, f1.x, acc[2]); acc[3] = fmaf(v, f1.y, acc[3]);
        acc[4] = fmaf(v, f2.x, acc[4]); acc[5] = fmaf(v, f2.y, acc[5]);
        acc[6] = fmaf(v, f3.x, acc[6]); acc[7] = fmaf(v, f3.y, acc[7]);
        acc[8] = fmaf(v, f4.x, acc[8]); acc[9] = fmaf(v, f4.y, acc[9]);
    }

    #pragma unroll
    for (int k = 0; k < C_DIM; k++)
        #pragma unroll
        for (int off = 16; off > 0; off >>= 1)
            acc[k] += __shfl_xor_sync(0xffffffff, acc[k], off);

    // self term (broadcast load, all lanes same address) + write
    const uint4 s0 = g_gh[(size_t)row * 2];
    const unsigned s4 = *(const unsigned*)&g_gh[(size_t)row * 2 + 1];
    float gs[C_DIM];
    {
        const float2 f0 = __half22float2(*(const __half2*)&s0.x);
        const float2 f1 = __half22float2(*(const __half2*)&s0.y);
        const float2 f2 = __half22float2(*(const __half2*)&s0.z);
        const float2 f3 = __half22float2(*(const __half2*)&s0.w);
        const float2 f4 = __half22float2(*(const __half2*)&s4);
        gs[0] = f0.x; gs[1] = f0.y; gs[2] = f1.x; gs[3] = f1.y;
        gs[4] = f2.x; gs[5] = f2.y; gs[6] = f3.x; gs[7] = f3.y;
        gs[8] = f4.x; gs[9] = f4.y;
    }

    const float c1 = 0.1f * (1.0f + eps1[0]);
    #pragma unroll
    for (int k = 0; k < C_DIM; k++)
        if (lane == k)
            out[(size_t)row * C_DIM + k] = fmaf(c1, gs[k], acc[k]);
}

// ---------------------------------------------------------------------------
// Launch. Inputs: x, rows0, cols0, vals0, rows1, cols1, vals1, W0, W1, eps0, eps1
// ---------------------------------------------------------------------------
extern "C" void kernel_launch(void* const* d_in, const int* in_sizes, int n_in,
                              void* d_out, int out_size) {
    const int*   rows0 = (const int*)  d_in[1];
    const int*   cols0 = (const int*)  d_in[2];
    const float* vals0 = (const float*)d_in[3];
    const int*   rows1 = (const int*)  d_in[4];
    const int*   cols1 = (const int*)  d_in[5];
    const float* vals1 = (const float*)d_in[6];
    const float* W0    = (const float*)d_in[7];
    const float* W1    = (const float*)d_in[8];
    const float* eps0  = (const float*)d_in[9];
    const float* eps1  = (const float*)d_in[10];
    float* out = (float*)d_out;

    void* cnt_ptr = nullptr;
    cudaGetSymbolAddress(&cnt_ptr, g_cnt);
    cudaMemsetAsync(cnt_ptr, 0, N_NODES * sizeof(int));

    k_convert<<<148 * 8, 256>>>((const float4*)W0);

    const int eb = (E2 + 255) / 256;                   // 6250
    k_scatter<<<eb, 256>>>(rows0, cols0, vals0, rows1, cols1, vals1);

    k_layer1<<<N_NODES / 8, 256>>>(W0, W1, eps0);      // warp per row
    k_layer2<<<N_NODES / 8, 256>>>(eps1, out);         // warp per row
}